// round 6
// baseline (speedup 1.0000x reference)
#include <cuda_runtime.h>
#include <cuda_bf16.h>

// B=16, N_VEC=2048, N_DIM=32, N_W=4, N_HID=128, VOCAB=32000, N_CLASS=10

typedef unsigned long long u64;

__device__ __forceinline__ u64 fma2(u64 a, u64 b, u64 c) {
    u64 d;
    asm("fma.rn.f32x2 %0, %1, %2, %3;" : "=l"(d) : "l"(a), "l"(b), "l"(c));
    return d;
}
__device__ __forceinline__ u64 add2(u64 a, u64 b) {
    u64 d;
    asm("add.rn.f32x2 %0, %1, %2;" : "=l"(d) : "l"(a), "l"(b));
    return d;
}
__device__ __forceinline__ u64 pack2(float lo, float hi) {
    u64 r;
    asm("mov.b64 %0, {%1, %2};" : "=l"(r) : "f"(lo), "f"(hi));
    return r;
}
__device__ __forceinline__ float2 unpack2(u64 v) {
    float2 f;
    asm("mov.b64 {%0, %1}, %2;" : "=f"(f.x), "=f"(f.y) : "l"(v));
    return f;
}

// ---------- scratch (device globals; allocation is forbidden) ----------
__device__ float g_X [16 * 2048 * 32];
__device__ float g_VA[16 * 2048 * 32];
__device__ float g_VB[16 * 2048 * 32];
__device__ float g_Upart[16 * 16 * 129 * 32];   // [b][chunk][129][32] (row 128 = bias c)
__device__ float g_U[16 * 129 * 32];            // [b][129][32]
__device__ float g_partF[16 * 32 * 10];
__device__ unsigned g_utick[16];
__device__ unsigned g_tick;

// ---------- X = emb[data], with per-block int64/int32 detection ----------
__global__ __launch_bounds__(256) void k_gather(const int* __restrict__ d32,
                                                const float* __restrict__ emb) {
    __shared__ int s_is64;
    int tid = threadIdx.x;
    if (tid == 0) s_is64 = 1;
    __syncthreads();
    if (tid < 32) { if (d32[2 * tid + 1] != 0) s_is64 = 0; }
    __syncthreads();
    int t = blockIdx.x * 256 + tid;              // over 16*2048*8 float4s
    int row = t >> 3, q = t & 7;
    int idx = s_is64 ? d32[row * 2] : d32[row];
    float4 v = *reinterpret_cast<const float4*>(emb + (size_t)idx * 32 + q * 4);
    *reinterpret_cast<float4*>(g_X + (size_t)row * 32 + q * 4) = v;
}

// ---------- U partials + folded cross-chunk reduction ----------
// grid (16 K-chunks, 16 batch), 256 threads; thread tile 4h x 4d, f32x2 along K(=m).
// Last-finishing block per batch reduces the 16 chunk partials into g_U.
__global__ __launch_bounds__(256) void k_upart(const float* __restrict__ fw2,
                                               const float* __restrict__ fb2,
                                               int vin_sel, int layer) {
    __shared__ __align__(16) float VsT[32 * 130];   // [d][m], pad 130
    __shared__ unsigned s_rank;
    int b = blockIdx.y, ch = blockIdx.x, tid = threadIdx.x;
    int m0 = ch * 128;
    const float* Vin = (vin_sel == 0) ? g_X : (vin_sel == 1 ? g_VA : g_VB);
    const float* vg = Vin + ((size_t)(b * 2048 + m0)) * 32;
#pragma unroll
    for (int it = 0; it < 16; ++it) {
        int t = tid + it * 256;                  // t = m*32 + d
        VsT[(t & 31) * 130 + (t >> 5)] = vg[t];
    }
    __syncthreads();

    int d0 = (tid & 7) * 4, h0 = (tid >> 3) * 4;
    const float* w0 = fw2 + ((size_t)(layer * 128 + h0)) * 2048 + m0;

    u64 acc[4][4];
#pragma unroll
    for (int a = 0; a < 4; ++a)
#pragma unroll
        for (int c = 0; c < 4; ++c) acc[a][c] = 0ull;

#pragma unroll 8
    for (int m = 0; m < 64; ++m) {               // 2 K-elems per iter
        u64 va[4];
#pragma unroll
        for (int kd = 0; kd < 4; ++kd)
            va[kd] = *reinterpret_cast<const u64*>(VsT + (d0 + kd) * 130 + 2 * m);
#pragma unroll
        for (int kh = 0; kh < 4; ++kh) {
            u64 w = *reinterpret_cast<const u64*>(w0 + (size_t)kh * 2048 + 2 * m);
#pragma unroll
            for (int kd = 0; kd < 4; ++kd) acc[kh][kd] = fma2(w, va[kd], acc[kh][kd]);
        }
    }

    float* up = g_Upart + (((size_t)(b * 16 + ch)) * 129 + h0) * 32 + d0;
#pragma unroll
    for (int kh = 0; kh < 4; ++kh) {
        float2 s0 = unpack2(acc[kh][0]), s1 = unpack2(acc[kh][1]);
        float2 s2 = unpack2(acc[kh][2]), s3 = unpack2(acc[kh][3]);
        *reinterpret_cast<float4*>(up + (size_t)kh * 32) =
            make_float4(s0.x + s0.y, s1.x + s1.y, s2.x + s2.y, s3.x + s3.y);
    }

    if (tid < 8) {                               // bias row c (h == 128)
        int db = tid * 4;
        const float* wb = fb2 + (size_t)layer * 2048 + m0;
        u64 a[4] = {0ull, 0ull, 0ull, 0ull};
        for (int m = 0; m < 64; ++m) {
            u64 w2 = *reinterpret_cast<const u64*>(wb + 2 * m);
#pragma unroll
            for (int k = 0; k < 4; ++k)
                a[k] = fma2(w2, *reinterpret_cast<const u64*>(VsT + (db + k) * 130 + 2 * m), a[k]);
        }
        float2 s0 = unpack2(a[0]), s1 = unpack2(a[1]), s2 = unpack2(a[2]), s3 = unpack2(a[3]);
        *reinterpret_cast<float4*>(g_Upart + (((size_t)(b * 16 + ch)) * 129 + 128) * 32 + db) =
            make_float4(s0.x + s0.y, s1.x + s1.y, s2.x + s2.y, s3.x + s3.y);
    }

    // ---- ticket: last block of this batch reduces the 16 chunks ----
    __threadfence();
    __syncthreads();
    if (tid == 0) s_rank = atomicAdd(&g_utick[b], 1u);
    __syncthreads();
    if (s_rank == 15u) {
        __threadfence();
        const float4* base = reinterpret_cast<const float4*>(g_Upart) + (size_t)b * 16 * 1032;
        float4* dst = reinterpret_cast<float4*>(g_U) + (size_t)b * 1032;
        for (int r4 = tid; r4 < 1032; r4 += 256) {
            float4 s = base[r4];
#pragma unroll
            for (int c = 1; c < 16; ++c) {
                float4 v = base[(size_t)c * 1032 + r4];
                s.x += v.x; s.y += v.y; s.z += v.z; s.w += v.w;
            }
            dst[r4] = s;
        }
        if (tid == 0) g_utick[b] = 0u;           // reset for next layer/replay
    }
}

// ---------- fused: H = gelu(X @ fw1 + fb1); V' = H @ U + c ----------
// 64 rows/block, 256 threads, grid (32,16). Phase 2 splits j across thread halves.
// dyn smem: Xs [64*32] (8KB) | Us [129*32] (16.5KB) | Hs [128][66] f32 (33.8KB) = 58496B
__global__ __launch_bounds__(256, 3) void k_vupd(const float* __restrict__ fw1,
                                                 const float* __restrict__ fb1,
                                                 int vout_sel, int layer) {
    extern __shared__ __align__(16) char smraw[];
    float* Xs = reinterpret_cast<float*>(smraw);            // [64][32]
    float* Us = Xs + 2048;                                  // [129][32]
    float* Hs = Us + 4128;                                  // [128][66]
    int b = blockIdx.y, n0 = blockIdx.x * 64, tid = threadIdx.x;

    const float4* xg = reinterpret_cast<const float4*>(g_X + ((size_t)(b * 2048 + n0)) * 32);
    reinterpret_cast<float4*>(Xs)[tid]       = xg[tid];
    reinterpret_cast<float4*>(Xs)[tid + 256] = xg[tid + 256];
    const float4* Ug = reinterpret_cast<const float4*>(g_U + (size_t)b * 4128);
#pragma unroll
    for (int it = 0; it < 4; ++it)
        reinterpret_cast<float4*>(Us)[tid + it * 256] = Ug[tid + it * 256];
    if (tid < 8) reinterpret_cast<float4*>(Us)[1024 + tid] = Ug[1024 + tid];
    __syncthreads();

    // phase 1: thread = 1 col j (tid&127), 32 rows (half tid>>7); f32x2 along d.
    {
        int j = tid & 127;
        int rbase = (tid >> 7) * 32;
        const float* w = fw1 + (size_t)layer * 4096 + j;
        u64 wcol[16];
#pragma unroll
        for (int k = 0; k < 16; ++k) wcol[k] = pack2(w[(2 * k) * 128], w[(2 * k + 1) * 128]);
        float bj = fb1[layer * 128 + j];
#pragma unroll 2
        for (int rr = 0; rr < 32; ++rr) {
            int r = rbase + rr;
            const ulonglong2* xq = reinterpret_cast<const ulonglong2*>(Xs + r * 32);
            u64 a = 0ull;
#pragma unroll
            for (int k = 0; k < 8; ++k) {
                ulonglong2 x = xq[k];
                a = fma2(x.x, wcol[2 * k], a);
                a = fma2(x.y, wcol[2 * k + 1], a);
            }
            float2 s = unpack2(a);
            float xv = s.x + s.y + bj;
            Hs[j * 66 + r] = 0.5f * xv * (1.0f + erff(xv * 0.7071067811865476f));
        }
    }
    __syncthreads();

    // phase 2: tile 4 rows x 4 cols; j split across thread halves; combine in smem.
    int jbase = (tid >> 7) * 64;
    int r0 = ((tid >> 3) & 15) * 4, d0 = (tid & 7) * 4;
    u64 acc[4][2];
#pragma unroll
    for (int k = 0; k < 4; ++k) { acc[k][0] = 0ull; acc[k][1] = 0ull; }
#pragma unroll 2
    for (int jj = 0; jj < 64; ++jj) {
        int j = jbase + jj;
        const float* hp = Hs + j * 66 + r0;
        float2 hA = *reinterpret_cast<const float2*>(hp);
        float2 hB = *reinterpret_cast<const float2*>(hp + 2);
        ulonglong2 u = *reinterpret_cast<const ulonglong2*>(Us + j * 32 + d0);
        u64 h0 = pack2(hA.x, hA.x), h1 = pack2(hA.y, hA.y);
        u64 h2 = pack2(hB.x, hB.x), h3 = pack2(hB.y, hB.y);
        acc[0][0] = fma2(h0, u.x, acc[0][0]);  acc[0][1] = fma2(h0, u.y, acc[0][1]);
        acc[1][0] = fma2(h1, u.x, acc[1][0]);  acc[1][1] = fma2(h1, u.y, acc[1][1]);
        acc[2][0] = fma2(h2, u.x, acc[2][0]);  acc[2][1] = fma2(h2, u.y, acc[2][1]);
        acc[3][0] = fma2(h3, u.x, acc[3][0]);  acc[3][1] = fma2(h3, u.y, acc[3][1]);
    }
    __syncthreads();                             // Hs region now dead -> combine buffer
    ulonglong2* buf = reinterpret_cast<ulonglong2*>(Hs);
    if (tid < 128) {
#pragma unroll
        for (int k = 0; k < 4; ++k) buf[k * 128 + tid] = make_ulonglong2(acc[k][0], acc[k][1]);
    }
    __syncthreads();
    if (tid >= 128) {
        int p = tid - 128;
        float* Vout = (vout_sel == 1) ? g_VA : g_VB;
        float4 c4 = *reinterpret_cast<const float4*>(Us + 4096 + d0);
#pragma unroll
        for (int k = 0; k < 4; ++k) {
            ulonglong2 o = buf[k * 128 + p];
            u64 s0 = add2(acc[k][0], o.x);
            u64 s1 = add2(acc[k][1], o.y);
            float2 p0 = unpack2(s0), p1 = unpack2(s1);
            *reinterpret_cast<float4*>(Vout + ((size_t)(b * 2048 + n0 + r0 + k)) * 32 + d0) =
                make_float4(p0.x + c4.x, p0.y + c4.y, p1.x + c4.z, p1.y + c4.w);
        }
    }
}

// ---------- final projection, fused partial + completion (ticket) ----------
__global__ __launch_bounds__(256) void k_fproj(const float* __restrict__ Wf,
                                               const float* __restrict__ bf,
                                               float* __restrict__ out) {
    __shared__ float wsum[8][10];
    __shared__ int s_last;
    int b = blockIdx.y, ch = blockIdx.x, tid = threadIdx.x;
    int lane = tid & 31, w = tid >> 5;
    float acc[10];
#pragma unroll
    for (int c = 0; c < 10; ++c) acc[c] = 0.f;
    const float* Vb = g_VB + (size_t)b * 65536 + ch * 2048;
#pragma unroll
    for (int q = 0; q < 8; ++q) {
        int k = q * 256 + tid;
        float v = Vb[k];
        const float* wr = Wf + (size_t)(ch * 2048 + k) * 10;
#pragma unroll
        for (int c = 0; c < 10; ++c) acc[c] += v * wr[c];
    }
#pragma unroll
    for (int c = 0; c < 10; ++c) {
#pragma unroll
        for (int s = 16; s > 0; s >>= 1) acc[c] += __shfl_down_sync(0xffffffffu, acc[c], s);
        if (lane == 0) wsum[w][c] = acc[c];
    }
    __syncthreads();
    if (tid < 10) {
        float s = 0.f;
#pragma unroll
        for (int ww = 0; ww < 8; ++ww) s += wsum[ww][tid];
        g_partF[((size_t)(b * 32 + ch)) * 10 + tid] = s;
    }
    __threadfence();
    __syncthreads();
    if (tid == 0) {
        unsigned prev = atomicAdd(&g_tick, 1u);
        s_last = (prev == 511u) ? 1 : 0;
    }
    __syncthreads();
    if (s_last) {
        __threadfence();
        if (tid < 160) {
            int bb = tid / 10, c = tid % 10;
            float s = bf[c];
#pragma unroll
            for (int cc = 0; cc < 32; ++cc) s += g_partF[((size_t)(bb * 32 + cc)) * 10 + c];
            out[tid] = s;
        }
        if (tid == 0) g_tick = 0u;   // reset for next graph replay
    }
}

extern "C" void kernel_launch(void* const* d_in, const int* in_sizes, int n_in,
                              void* d_out, int out_size) {
    const int*   data = (const int*)  d_in[0];
    const float* emb  = (const float*)d_in[1];
    const float* fw1  = (const float*)d_in[2];
    const float* fb1  = (const float*)d_in[3];
    const float* fw2  = (const float*)d_in[4];
    const float* fb2  = (const float*)d_in[5];
    const float* Wf   = (const float*)d_in[6];
    const float* bf   = (const float*)d_in[7];
    float* out = (float*)d_out;

    const int VUPD_SMEM = (2048 + 4128 + 128 * 66) * 4;   // 58496 bytes -> 3 blocks/SM
    cudaFuncSetAttribute(k_vupd, cudaFuncAttributeMaxDynamicSharedMemorySize, VUPD_SMEM);

    k_gather<<<1024, 256>>>(data, emb);

    // layers i = 3,2,1,0 ; V ping-pong: X -> VA -> VB -> VA -> VB
    int vin = 0;
    for (int it = 0; it < 4; ++it) {
        int layer = 3 - it;
        int vout = (vin == 1) ? 2 : 1;
        k_upart<<<dim3(16, 16), 256>>>(fw2, fb2, vin, layer);
        k_vupd<<<dim3(32, 16), 256, VUPD_SMEM>>>(fw1, fb1, vout, layer);
        vin = vout;
    }

    k_fproj<<<dim3(32, 16), 256>>>(Wf, bf, out);
}